// round 6
// baseline (speedup 1.0000x reference)
#include <cuda_runtime.h>

// LocalVariation: out[b, k, y, x] = x[b,0,y,x] - x_pad[b,0,y+i,x+j]
// 24 off-center (i,j) in 5x5 window, replicate padding.
// x [16,1,512,512] f32 -> out [16,24,512,512] f32.
//
// R6: tall tiles to amortize input-side L1 work and per-block overhead.
// 128 x {22,23} tiles, 3 rows/thread via rolling 5-row register window:
//   halo ratio 26.5/22.5 = 1.18 (R5: 1.27), LDS 4.67/row (R5: 6/row),
//   1472 blocks -> 1.99 waves at 5 blocks/SM -> ~0.7% tail.
// launch_bounds(256,5) pins regs <=51 so occupancy stays 5.

#define HH 512
#define WW 512
#define NB 16
#define NC 24
#define TX 128    // tile width (32 threads x float4)
#define SW 132    // TX + 4 halo
#define SHMAX 27  // max tile height (23) + 4 halo

__global__ __launch_bounds__(256, 5)
void local_variation_kernel(const float* __restrict__ x, float* __restrict__ out) {
    __shared__ float s[SHMAX][SW];

    const int tid = threadIdx.y * 32 + threadIdx.x;
    const int x0 = blockIdx.x * TX;
    const int by = blockIdx.y;
    const int b  = blockIdx.z;

    // Non-uniform tile heights: by 0..5 -> 23 rows; by 6..22 -> 22 rows.
    const int h  = (by < 6) ? 23 : 22;
    const int y0 = (by < 6) ? (23 * by) : (138 + 22 * (by - 6));
    const int sh = h + 4;

    const float* __restrict__ xb = x + (size_t)b * HH * WW;

    // Cooperative halo load with replicate-pad clamping. sh*SW elems (<=3564).
    for (int idx = tid; idx < sh * SW; idx += 256) {
        int r = idx / SW;
        int c = idx - r * SW;
        int gy = min(max(y0 + r - 2, 0), HH - 1);
        int gx = min(max(x0 + c - 2, 0), WW - 1);
        s[r][c] = xb[gy * WW + gx];
    }
    __syncthreads();

    const int sx = threadIdx.x * 4;   // tile-local col of first pixel
    const int rb = threadIdx.y * 3;   // first output row (tile-local), 0..21
    const int nrows = min(3, h - rb); // rows this warp produces (warp-uniform, >=1)

    // 5-row x 8-float rolling register window.
    // Invariant at step t: slot (t+i)%5 holds smem row rb+t+i.
    float w[5][8];
    #pragma unroll
    for (int i = 0; i < 5; i++) {
        float4 lo = *reinterpret_cast<const float4*>(&s[rb + i][sx]);
        float4 hi = *reinterpret_cast<const float4*>(&s[rb + i][sx + 4]);
        w[i][0] = lo.x; w[i][1] = lo.y; w[i][2] = lo.z; w[i][3] = lo.w;
        w[i][4] = hi.x; w[i][5] = hi.y; w[i][6] = hi.z; w[i][7] = hi.w;
    }

    const int gy0 = y0 + rb;
    const int gx  = x0 + sx;
    float* __restrict__ ob = out + (((size_t)b * NC) * HH + gy0) * WW + gx;
    const size_t plane = (size_t)HH * WW;

    #pragma unroll
    for (int t = 0; t < 3; t++) {
        if (t >= nrows) break;   // warp-uniform

        const float* cw = w[(t + 2) % 5];
        const float c0 = cw[2], c1 = cw[3], c2 = cw[4], c3 = cw[5];

        float* __restrict__ orow = ob + t * WW;
        int k = 0;
        #pragma unroll
        for (int i = 0; i < 5; i++) {
            const float* rr = w[(t + i) % 5];
            #pragma unroll
            for (int j = 0; j < 5; j++) {
                if (i == 2 && j == 2) continue;
                float4 o;
                o.x = c0 - rr[j + 0];
                o.y = c1 - rr[j + 1];
                o.z = c2 - rr[j + 2];
                o.w = c3 - rr[j + 3];
                __stcs(reinterpret_cast<float4*>(orow + (size_t)k * plane), o);
                k++;
            }
        }

        // Roll: slot t%5 (held row rb+t) <- smem row rb+t+5, if next step runs.
        if (t < 2 && (t + 1) < nrows) {
            float4 lo = *reinterpret_cast<const float4*>(&s[rb + t + 5][sx]);
            float4 hi = *reinterpret_cast<const float4*>(&s[rb + t + 5][sx + 4]);
            float* d = w[t % 5];
            d[0] = lo.x; d[1] = lo.y; d[2] = lo.z; d[3] = lo.w;
            d[4] = hi.x; d[5] = hi.y; d[6] = hi.z; d[7] = hi.w;
        }
    }
}

extern "C" void kernel_launch(void* const* d_in, const int* in_sizes, int n_in,
                              void* d_out, int out_size) {
    const float* x = (const float*)d_in[0];
    float* out = (float*)d_out;
    dim3 block(32, 8, 1);
    dim3 grid(WW / TX, 23, NB);   // 4 x 23 x 16 = 1472 blocks
    local_variation_kernel<<<grid, block>>>(x, out);
}